// round 9
// baseline (speedup 1.0000x reference)
#include <cuda_runtime.h>
#include <cuda_bf16.h>
#include <cstdint>
#include <cstddef>

// Problem constants
#define B_SZ   2
#define T_SEQ  2048
#define D_MOD  1024
#define NH     16
#define DH     64
#define M_TOT  (B_SZ * T_SEQ)   // 4096 rows
#define NCOL   (NH * DH)        // 1024 cols (== D_MOD)

// ---------------------------------------------------------------------------
// Scratch carve (bytes):
//   q: 0  k: 16MB  v: 32MB  attn: 48MB  xr: 64MB  wqkvT: 80MB(12MB)  woT: 92MB
#define SCRATCH_BYTES (96u * 1024u * 1024u)
__device__ __align__(256) unsigned char g_scratch[SCRATCH_BYTES];

// ---------------------------------------------------------------------------
__device__ __forceinline__ float tf32_rna(float v) {
    uint32_t u;
    asm("cvt.rna.tf32.f32 %0, %1;" : "=r"(u) : "f"(v));
    return __uint_as_float(u);
}

#define MMA_TF32(D, A, B)                                                   \
    asm volatile(                                                           \
        "mma.sync.aligned.m16n8k8.row.col.f32.tf32.tf32.f32 "               \
        "{%0,%1,%2,%3}, {%4,%5,%6,%7}, {%8,%9}, {%0,%1,%2,%3};"             \
        : "+f"((D)[0]), "+f"((D)[1]), "+f"((D)[2]), "+f"((D)[3])            \
        : "r"((A)[0]), "r"((A)[1]), "r"((A)[2]), "r"((A)[3]),               \
          "r"((B)[0]), "r"((B)[1]))

#define CP_ASYNC16(sdst, gsrc)                                              \
    asm volatile("cp.async.cg.shared.global [%0], [%1], 16;"                \
                 :: "r"((uint32_t)__cvta_generic_to_shared(sdst)), "l"(gsrc))

// ---------------------------------------------------------------------------
// Elementwise tf32 rounding (x -> xr), vectorized x4
// ---------------------------------------------------------------------------
__global__ __launch_bounds__(256)
void round_tf32_4(const float* __restrict__ in, float* __restrict__ out, int n4) {
    int i = blockIdx.x * blockDim.x + threadIdx.x;
    if (i >= n4) return;
    float4 v = ((const float4*)in)[i];
    v.x = tf32_rna(v.x);
    v.y = tf32_rna(v.y);
    v.z = tf32_rna(v.z);
    v.w = tf32_rna(v.w);
    ((float4*)out)[i] = v;
}

// ---------------------------------------------------------------------------
// Weight transpose + tf32 round: w[K][N] -> wT[N][K]
// ---------------------------------------------------------------------------
__global__ __launch_bounds__(256)
void cvt_T(const float* __restrict__ w, float* __restrict__ wt) {
    __shared__ float t[32][33];
    const int n0 = blockIdx.x * 32;
    const int k0 = blockIdx.y * 32;
    const int tx = threadIdx.x;
    const int ty = threadIdx.y;
    #pragma unroll
    for (int i = 0; i < 32; i += 8)
        t[ty + i][tx] = w[(size_t)(k0 + ty + i) * NCOL + n0 + tx];
    __syncthreads();
    #pragma unroll
    for (int i = 0; i < 32; i += 8) {
        float v = t[tx][ty + i];
        wt[(size_t)(n0 + ty + i) * D_MOD + k0 + tx] = tf32_rna(v);
    }
}

// ---------------------------------------------------------------------------
// GEMM core pieces (128x128 CTA tile, BK=16, 3-stage cp.async ring,
// 256 threads = 8 warps of 64x32 warp tiles). Shared by both GEMM kernels.
// Dynamic smem: As[3][128][20] | Bs[3][128][20]  (61,440 bytes)
// ---------------------------------------------------------------------------
#define GP 20
#define GSTG 3
#define GEMM_SMEM (GSTG * 128 * GP * 2 * 4)
#define NKC (D_MOD / 16)   // 64

#define GEMM_PROLOG()                                                        \
    extern __shared__ float gsm[];                                           \
    float (*As)[128][GP] = (float (*)[128][GP])gsm;                          \
    float (*Bs)[128][GP] = (float (*)[128][GP])(gsm + GSTG * 128 * GP);      \
    const int tid  = threadIdx.x;                                            \
    const int lane = tid & 31;                                               \
    const int wid  = tid >> 5;                                               \
    const int wm   = wid >> 2;                                               \
    const int wn   = wid & 3;                                                \
    const int g    = lane >> 2;                                              \
    float acc[4][4][4];                                                      \
    _Pragma("unroll")                                                        \
    for (int mt = 0; mt < 4; ++mt)                                           \
        _Pragma("unroll")                                                    \
        for (int nt = 0; nt < 4; ++nt)                                       \
            _Pragma("unroll")                                                \
            for (int r = 0; r < 4; ++r) acc[mt][nt][r] = 0.f

#define GEMM_ISSUE(kc, st)                                                   \
    do {                                                                     \
        _Pragma("unroll")                                                    \
        for (int it = 0; it < 2; ++it) {                                     \
            int idx = tid + it * 256;                                        \
            int row = idx >> 2, seg = (idx & 3) * 4;                         \
            CP_ASYNC16(&As[st][row][seg],                                    \
                       Ap + (size_t)(m0 + row) * D_MOD + (kc) * 16 + seg);   \
            CP_ASYNC16(&Bs[st][row][seg],                                    \
                       Bp + (size_t)(n0g + row) * D_MOD + (kc) * 16 + seg);  \
        }                                                                    \
        asm volatile("cp.async.commit_group;");                              \
    } while (0)

#define GEMM_MAINLOOP()                                                      \
    GEMM_ISSUE(0, 0);                                                        \
    GEMM_ISSUE(1, 1);                                                        \
    for (int kc = 0; kc < NKC; ++kc) {                                       \
        if (kc < NKC - 1) asm volatile("cp.async.wait_group 1;");            \
        else              asm volatile("cp.async.wait_group 0;");            \
        __syncthreads();                                                     \
        if (kc + 2 < NKC) {                                                  \
            int st2 = kc + 2; st2 -= (st2 >= GSTG) ? GSTG : 0;               \
            st2 -= (st2 >= GSTG) ? GSTG : 0;  /* kc+2 < 66 -> ok */          \
            GEMM_ISSUE(kc + 2, (kc + 2) % GSTG);                             \
        }                                                                    \
        const int st = kc % GSTG;                                            \
        _Pragma("unroll")                                                    \
        for (int ks = 0; ks < 2; ++ks) {                                     \
            const int ac = ks * 8 + (lane & 3);                              \
            uint32_t a[4][4], b[4][2];                                       \
            _Pragma("unroll")                                                \
            for (int mt = 0; mt < 4; ++mt) {                                 \
                const int r = wm * 64 + mt * 16 + g;                         \
                a[mt][0] = __float_as_uint(As[st][r][ac]);                   \
                a[mt][1] = __float_as_uint(As[st][r + 8][ac]);               \
                a[mt][2] = __float_as_uint(As[st][r][ac + 4]);               \
                a[mt][3] = __float_as_uint(As[st][r + 8][ac + 4]);           \
            }                                                                \
            _Pragma("unroll")                                                \
            for (int nt = 0; nt < 4; ++nt) {                                 \
                const int n = wn * 32 + nt * 8 + g;                          \
                b[nt][0] = __float_as_uint(Bs[st][n][ac]);                   \
                b[nt][1] = __float_as_uint(Bs[st][n][ac + 4]);               \
            }                                                                \
            _Pragma("unroll")                                                \
            for (int mt = 0; mt < 4; ++mt)                                   \
                _Pragma("unroll")                                            \
                for (int nt = 0; nt < 4; ++nt)                               \
                    MMA_TF32(acc[mt][nt], a[mt], b[nt]);                     \
        }                                                                    \
    }

// ---------------------------------------------------------------------------
// Fused QKV GEMM: Bt = wqkvT [3*1024][1024]; blockIdx.x selects matrix third.
// Epilogue tf32-rounds outputs; Q additionally gets the 0.125 softmax scale.
// ---------------------------------------------------------------------------
__global__ __launch_bounds__(256)
void gemm_qkv(const float* __restrict__ Ap, const float* __restrict__ Bp_all,
              const float* __restrict__ bq, const float* __restrict__ bk,
              const float* __restrict__ bv,
              float* __restrict__ qo, float* __restrict__ ko,
              float* __restrict__ vo) {
    const int m0  = blockIdx.y * 128;
    const int n0g = blockIdx.x * 128;          // row in fused wT
    const int mat = blockIdx.x >> 3;           // 0=q 1=k 2=v
    const int n0  = (blockIdx.x & 7) * 128;    // col within output matrix
    const float* Bp   = Bp_all;
    const float* bias = (mat == 0) ? bq : (mat == 1) ? bk : bv;
    float* C          = (mat == 0) ? qo : (mat == 1) ? ko : vo;
    const float osc   = (mat == 0) ? 0.125f : 1.0f;

    GEMM_PROLOG();
    GEMM_MAINLOOP();

    #pragma unroll
    for (int mt = 0; mt < 4; ++mt) {
        const int r0 = m0 + wm * 64 + mt * 16 + g;
        #pragma unroll
        for (int nt = 0; nt < 4; ++nt) {
            const int col = n0 + wn * 32 + nt * 8 + (lane & 3) * 2;
            const float2 bv2 = *(const float2*)&bias[col];
            float2 o0, o1;
            o0.x = tf32_rna((acc[mt][nt][0] + bv2.x) * osc);
            o0.y = tf32_rna((acc[mt][nt][1] + bv2.y) * osc);
            o1.x = tf32_rna((acc[mt][nt][2] + bv2.x) * osc);
            o1.y = tf32_rna((acc[mt][nt][3] + bv2.y) * osc);
            *(float2*)&C[(size_t)r0 * NCOL + col] = o0;
            *(float2*)&C[(size_t)(r0 + 8) * NCOL + col] = o1;
        }
    }
}

// ---------------------------------------------------------------------------
// Plain GEMM (output projection): fp32 out, no rounding.
// ---------------------------------------------------------------------------
__global__ __launch_bounds__(256)
void gemm_tf32(const float* __restrict__ Ap, const float* __restrict__ Bp,
               const float* __restrict__ bias, float* __restrict__ C) {
    const int m0  = blockIdx.y * 128;
    const int n0g = blockIdx.x * 128;
    const int n0  = n0g;

    GEMM_PROLOG();
    GEMM_MAINLOOP();

    #pragma unroll
    for (int mt = 0; mt < 4; ++mt) {
        const int r0 = m0 + wm * 64 + mt * 16 + g;
        #pragma unroll
        for (int nt = 0; nt < 4; ++nt) {
            const int col = n0 + wn * 32 + nt * 8 + (lane & 3) * 2;
            const float2 bv2 = *(const float2*)&bias[col];
            float2 o0, o1;
            o0.x = acc[mt][nt][0] + bv2.x;
            o0.y = acc[mt][nt][1] + bv2.y;
            o1.x = acc[mt][nt][2] + bv2.x;
            o1.y = acc[mt][nt][3] + bv2.y;
            *(float2*)&C[(size_t)r0 * NCOL + col] = o0;
            *(float2*)&C[(size_t)(r0 + 8) * NCOL + col] = o1;
        }
    }
}

// ---------------------------------------------------------------------------
// Causal flash attention on tf32 mma.sync. Inputs are ALREADY tf32-rounded
// (and Q pre-scaled by 0.125), so loads are plain copies.
// ---------------------------------------------------------------------------
#define QP 68
#define VP 72
#define FA_SMEM ((64 * QP + 64 * QP + 64 * VP) * 4)

__global__ __launch_bounds__(128)
void flash_attn_mma(const float* __restrict__ q, const float* __restrict__ k,
                    const float* __restrict__ v, float* __restrict__ o) {
    const int qt = (int)gridDim.x - 1 - blockIdx.x;  // long CTAs first
    const int h  = blockIdx.y;
    const int b  = blockIdx.z;

    extern __shared__ float sm[];
    float* Qs = sm;              // 64 x QP (reused as Ps after frag hoist)
    float* Ks = sm + 64 * QP;
    float* Vs = Ks + 64 * QP;
    float* Ps = Qs;

    const int tid  = threadIdx.x;
    const int lane = tid & 31;
    const int w    = tid >> 5;
    const int g    = lane >> 2;
    const int t    = lane & 3;
    const int w16  = w * 16;
    const int q0   = qt * 64;

    #pragma unroll
    for (int it = 0; it < 8; ++it) {
        int idx = tid + it * 128;
        int row = idx >> 4, c4 = (idx & 15) * 4;
        *(float4*)&Qs[row * QP + c4] =
            *(const float4*)&q[(size_t)(b * T_SEQ + q0 + row) * NCOL + h * DH + c4];
    }
    __syncthreads();

    uint32_t qa[8][4];
    #pragma unroll
    for (int ks = 0; ks < 8; ++ks) {
        const int c = ks * 8 + t;
        qa[ks][0] = __float_as_uint(Qs[(w16 + g) * QP + c]);
        qa[ks][1] = __float_as_uint(Qs[(w16 + g + 8) * QP + c]);
        qa[ks][2] = __float_as_uint(Qs[(w16 + g) * QP + c + 4]);
        qa[ks][3] = __float_as_uint(Qs[(w16 + g + 8) * QP + c + 4]);
    }

    float mA = -1e30f, mB = -1e30f, lA = 0.f, lB = 0.f;
    float oacc[8][4];
    #pragma unroll
    for (int nt = 0; nt < 8; ++nt)
        #pragma unroll
        for (int r = 0; r < 4; ++r) oacc[nt][r] = 0.f;

    for (int kt = 0; kt <= qt; ++kt) {
        __syncthreads();

        #pragma unroll
        for (int it = 0; it < 8; ++it) {
            int idx = tid + it * 128;
            int row = idx >> 4, c4 = (idx & 15) * 4;
            size_t base = (size_t)(b * T_SEQ + kt * 64 + row) * NCOL + h * DH + c4;
            *(float4*)&Ks[row * QP + c4] = *(const float4*)&k[base];
            *(float4*)&Vs[row * VP + c4] = *(const float4*)&v[base];
        }
        __syncthreads();

        float sacc[8][4];
        #pragma unroll
        for (int nt = 0; nt < 8; ++nt)
            #pragma unroll
            for (int r = 0; r < 4; ++r) sacc[nt][r] = 0.f;

        #pragma unroll
        for (int ks = 0; ks < 8; ++ks) {
            const int c = ks * 8 + t;
            #pragma unroll
            for (int nt = 0; nt < 8; ++nt) {
                uint32_t bb[2];
                bb[0] = __float_as_uint(Ks[(nt * 8 + g) * QP + c]);
                bb[1] = __float_as_uint(Ks[(nt * 8 + g) * QP + c + 4]);
                MMA_TF32(sacc[nt], qa[ks], bb);
            }
        }

        if (kt == qt) {
            const int rA = w16 + g, rB = rA + 8;
            #pragma unroll
            for (int nt = 0; nt < 8; ++nt) {
                const int c0 = nt * 8 + 2 * t, c1 = c0 + 1;
                if (c0 > rA) sacc[nt][0] = -1e30f;
                if (c1 > rA) sacc[nt][1] = -1e30f;
                if (c0 > rB) sacc[nt][2] = -1e30f;
                if (c1 > rB) sacc[nt][3] = -1e30f;
            }
        }

        float rmA = -1e30f, rmB = -1e30f;
        #pragma unroll
        for (int nt = 0; nt < 8; ++nt) {
            rmA = fmaxf(rmA, fmaxf(sacc[nt][0], sacc[nt][1]));
            rmB = fmaxf(rmB, fmaxf(sacc[nt][2], sacc[nt][3]));
        }
        rmA = fmaxf(rmA, __shfl_xor_sync(0xffffffffu, rmA, 1));
        rmA = fmaxf(rmA, __shfl_xor_sync(0xffffffffu, rmA, 2));
        rmB = fmaxf(rmB, __shfl_xor_sync(0xffffffffu, rmB, 1));
        rmB = fmaxf(rmB, __shfl_xor_sync(0xffffffffu, rmB, 2));

        const float mnA = fmaxf(mA, rmA);
        const float mnB = fmaxf(mB, rmB);
        const float cA = __expf(mA - mnA);
        const float cB = __expf(mB - mnB);

        float sA = 0.f, sB = 0.f;
        #pragma unroll
        for (int nt = 0; nt < 8; ++nt) {
            sacc[nt][0] = __expf(sacc[nt][0] - mnA);
            sacc[nt][1] = __expf(sacc[nt][1] - mnA);
            sacc[nt][2] = __expf(sacc[nt][2] - mnB);
            sacc[nt][3] = __expf(sacc[nt][3] - mnB);
            sA += sacc[nt][0] + sacc[nt][1];
            sB += sacc[nt][2] + sacc[nt][3];
        }
        sA += __shfl_xor_sync(0xffffffffu, sA, 1);
        sA += __shfl_xor_sync(0xffffffffu, sA, 2);
        sB += __shfl_xor_sync(0xffffffffu, sB, 1);
        sB += __shfl_xor_sync(0xffffffffu, sB, 2);
        lA = lA * cA + sA;
        lB = lB * cB + sB;
        mA = mnA;
        mB = mnB;

        #pragma unroll
        for (int nt = 0; nt < 8; ++nt) {
            oacc[nt][0] *= cA; oacc[nt][1] *= cA;
            oacc[nt][2] *= cB; oacc[nt][3] *= cB;
        }

        #pragma unroll
        for (int nt = 0; nt < 8; ++nt) {
            const int c0 = nt * 8 + 2 * t;
            float2 p0, p1;
            p0.x = tf32_rna(sacc[nt][0]); p0.y = tf32_rna(sacc[nt][1]);
            p1.x = tf32_rna(sacc[nt][2]); p1.y = tf32_rna(sacc[nt][3]);
            *(float2*)&Ps[(w16 + g) * QP + c0]     = p0;
            *(float2*)&Ps[(w16 + g + 8) * QP + c0] = p1;
        }
        __syncwarp();

        #pragma unroll
        for (int ks = 0; ks < 8; ++ks) {
            const int c = ks * 8 + t;
            uint32_t pa[4];
            pa[0] = __float_as_uint(Ps[(w16 + g) * QP + c]);
            pa[1] = __float_as_uint(Ps[(w16 + g + 8) * QP + c]);
            pa[2] = __float_as_uint(Ps[(w16 + g) * QP + c + 4]);
            pa[3] = __float_as_uint(Ps[(w16 + g + 8) * QP + c + 4]);
            #pragma unroll
            for (int nt = 0; nt < 8; ++nt) {
                uint32_t bb[2];
                bb[0] = __float_as_uint(Vs[(ks * 8 + t) * VP + nt * 8 + g]);
                bb[1] = __float_as_uint(Vs[(ks * 8 + t + 4) * VP + nt * 8 + g]);
                MMA_TF32(oacc[nt], pa, bb);
            }
        }
        __syncwarp();
    }

    const float invA = 1.0f / lA;
    const float invB = 1.0f / lB;
    const int rA = b * T_SEQ + q0 + w16 + g;
    const int rB = rA + 8;
    #pragma unroll
    for (int nt = 0; nt < 8; ++nt) {
        const int col = h * DH + nt * 8 + 2 * t;
        float2 o0, o1;
        o0.x = tf32_rna(oacc[nt][0] * invA);
        o0.y = tf32_rna(oacc[nt][1] * invA);
        o1.x = tf32_rna(oacc[nt][2] * invB);
        o1.y = tf32_rna(oacc[nt][3] * invB);
        *(float2*)&o[(size_t)rA * NCOL + col] = o0;
        *(float2*)&o[(size_t)rB * NCOL + col] = o1;
    }
}

// ---------------------------------------------------------------------------
// Launch
// ---------------------------------------------------------------------------
extern "C" void kernel_launch(void* const* d_in, const int* in_sizes, int n_in,
                              void* d_out, int out_size) {
    const float* x  = (const float*)d_in[0];
    const float* wq = (const float*)d_in[1];
    const float* bq = (const float*)d_in[2];
    const float* wk = (const float*)d_in[3];
    const float* bk = (const float*)d_in[4];
    const float* wv = (const float*)d_in[5];
    const float* bv = (const float*)d_in[6];
    const float* wo = (const float*)d_in[7];
    const float* bo = (const float*)d_in[8];
    float* out = (float*)d_out;

    unsigned char* sp;
    cudaGetSymbolAddress((void**)&sp, g_scratch);
    const size_t MB = 1024u * 1024u;
    float* qp    = (float*)(sp + 0 * MB);
    float* kp    = (float*)(sp + 16 * MB);
    float* vp    = (float*)(sp + 32 * MB);
    float* ap    = (float*)(sp + 48 * MB);
    float* xr    = (float*)(sp + 64 * MB);
    float* wqkvT = (float*)(sp + 80 * MB);   // 3 x 4MB contiguous
    float* woT   = (float*)(sp + 92 * MB);

    cudaFuncSetAttribute(flash_attn_mma,
                         cudaFuncAttributeMaxDynamicSharedMemorySize, FA_SMEM);
    cudaFuncSetAttribute(gemm_qkv,
                         cudaFuncAttributeMaxDynamicSharedMemorySize, GEMM_SMEM);
    cudaFuncSetAttribute(gemm_tf32,
                         cudaFuncAttributeMaxDynamicSharedMemorySize, GEMM_SMEM);

    // 1) Round x to tf32
    const int n4 = M_TOT * D_MOD / 4;
    round_tf32_4<<<(n4 + 255) / 256, 256>>>(x, xr, n4);

    // 2) Transpose + round weights -> wT[N][K] (q,k,v fused region + wo)
    dim3 tg(NCOL / 32, D_MOD / 32), tb(32, 8);
    cvt_T<<<tg, tb>>>(wq, wqkvT);
    cvt_T<<<tg, tb>>>(wk, wqkvT + 1024 * 1024);
    cvt_T<<<tg, tb>>>(wv, wqkvT + 2 * 1024 * 1024);
    cvt_T<<<tg, tb>>>(wo, woT);

    // 3) Fused QKV projection (rounded outputs; Q pre-scaled by 0.125)
    gemm_qkv<<<dim3(24, M_TOT / 128), 256, GEMM_SMEM>>>(
        xr, wqkvT, bq, bk, bv, qp, kp, vp);

    // 4) Attention on tensor cores
    flash_attn_mma<<<dim3(T_SEQ / 64, NH, B_SZ), 128, FA_SMEM>>>(qp, kp, vp, ap);

    // 5) Output projection
    gemm_tf32<<<dim3(NCOL / 128, M_TOT / 128), 256, GEMM_SMEM>>>(ap, woT, bo, out);
}

// round 10
// speedup vs baseline: 1.9325x; 1.9325x over previous
#include <cuda_runtime.h>
#include <cuda_fp16.h>
#include <cstdint>
#include <cstddef>

// Problem constants
#define B_SZ   2
#define T_SEQ  2048
#define D_MOD  1024
#define NH     16
#define DH     64
#define M_TOT  (B_SZ * T_SEQ)   // 4096
#define NCOL   (NH * DH)        // 1024

// ---------------------------------------------------------------------------
// Scratch carve (bytes), all fp16 intermediates:
//   q:0 (8MB)  k:8MB  v:16MB  attn:24MB  xh:32MB (8MB)  wqkvT:40MB (6MB)  woT:46MB
#define SCRATCH_BYTES (48u * 1024u * 1024u)
__device__ __align__(256) unsigned char g_scratch[SCRATCH_BYTES];

// ---------------------------------------------------------------------------
#define MMA_F16(D, A, B)                                                     \
    asm volatile(                                                            \
        "mma.sync.aligned.m16n8k16.row.col.f32.f16.f16.f32 "                 \
        "{%0,%1,%2,%3}, {%4,%5,%6,%7}, {%8,%9}, {%0,%1,%2,%3};"              \
        : "+f"((D)[0]), "+f"((D)[1]), "+f"((D)[2]), "+f"((D)[3])             \
        : "r"((A)[0]), "r"((A)[1]), "r"((A)[2]), "r"((A)[3]),                \
          "r"((B)[0]), "r"((B)[1]))

#define LDSM_X4(R, addr)                                                     \
    asm volatile("ldmatrix.sync.aligned.m8n8.x4.shared.b16 {%0,%1,%2,%3}, [%4];" \
        : "=r"((R)[0]), "=r"((R)[1]), "=r"((R)[2]), "=r"((R)[3]) : "r"(addr))

#define LDSM_X4_T(R, addr)                                                   \
    asm volatile("ldmatrix.sync.aligned.m8n8.x4.trans.shared.b16 {%0,%1,%2,%3}, [%4];" \
        : "=r"((R)[0]), "=r"((R)[1]), "=r"((R)[2]), "=r"((R)[3]) : "r"(addr))

#define CP_ASYNC16(sdst, gsrc)                                               \
    asm volatile("cp.async.cg.shared.global [%0], [%1], 16;"                 \
                 :: "r"((uint32_t)__cvta_generic_to_shared(sdst)), "l"(gsrc))

__device__ __forceinline__ uint32_t pack_h2(float lo, float hi) {
    __half2 h = __floats2half2_rn(lo, hi);
    return *reinterpret_cast<uint32_t*>(&h);
}

// ---------------------------------------------------------------------------
// fp32 -> fp16, vectorized x4
// ---------------------------------------------------------------------------
__global__ __launch_bounds__(256)
void cvt_half4(const float* __restrict__ in, __half* __restrict__ out, int n4) {
    int i = blockIdx.x * blockDim.x + threadIdx.x;
    if (i >= n4) return;
    float4 v = ((const float4*)in)[i];
    uint2 u;
    u.x = pack_h2(v.x, v.y);
    u.y = pack_h2(v.z, v.w);
    ((uint2*)out)[i] = u;
}

// ---------------------------------------------------------------------------
// Weight transpose + fp16: w[K][N] fp32 -> wT[N][K] fp16
// ---------------------------------------------------------------------------
__global__ __launch_bounds__(256)
void cvt_T_half(const float* __restrict__ w, __half* __restrict__ wt) {
    __shared__ float t[32][33];
    const int n0 = blockIdx.x * 32;
    const int k0 = blockIdx.y * 32;
    const int tx = threadIdx.x;
    const int ty = threadIdx.y;
    #pragma unroll
    for (int i = 0; i < 32; i += 8)
        t[ty + i][tx] = w[(size_t)(k0 + ty + i) * NCOL + n0 + tx];
    __syncthreads();
    #pragma unroll
    for (int i = 0; i < 32; i += 8)
        wt[(size_t)(n0 + ty + i) * D_MOD + k0 + tx] = __float2half_rn(t[tx][ty + i]);
}

// ---------------------------------------------------------------------------
// fp16 GEMM core: 128x128 CTA tile, BK=32, 3-stage cp.async, 256 threads
// (8 warps, 64x32 warp tiles), ldmatrix frags, m16n8k16 HMMA.
// smem: 3 stages x (A 128x40 + B 128x40) halves = 61,440 bytes
// ---------------------------------------------------------------------------
#define GP16 40
#define GSTG 3
#define GSTAGE (128 * GP16)
#define GEMM_SMEM (GSTG * GSTAGE * 2 * 2)
#define NKC16 (D_MOD / 32)   // 32

__device__ __forceinline__ void gemm16_core(
    const __half* __restrict__ Ap, const __half* __restrict__ Bp,
    int m0, int n0g, float acc[4][4][4]) {
    extern __shared__ __half hsm[];
    __half* sA = hsm;
    __half* sB = hsm + GSTG * GSTAGE;

    const int tid  = threadIdx.x;
    const int lane = tid & 31;
    const int wid  = tid >> 5;
    const int wm   = wid >> 2;
    const int wn   = wid & 3;
    const int lrow = lane & 15;
    const int lcol = (lane >> 4) * 8;

    #pragma unroll
    for (int mt = 0; mt < 4; ++mt)
        #pragma unroll
        for (int nt = 0; nt < 4; ++nt)
            #pragma unroll
            for (int r = 0; r < 4; ++r) acc[mt][nt][r] = 0.f;

    auto issue = [&](int kc, int st) {
        #pragma unroll
        for (int it = 0; it < 2; ++it) {
            int idx = tid + it * 256;
            int row = idx >> 2, ch = (idx & 3) * 8;
            CP_ASYNC16(sA + st * GSTAGE + row * GP16 + ch,
                       Ap + (size_t)(m0 + row) * D_MOD + kc * 32 + ch);
            CP_ASYNC16(sB + st * GSTAGE + row * GP16 + ch,
                       Bp + (size_t)(n0g + row) * D_MOD + kc * 32 + ch);
        }
        asm volatile("cp.async.commit_group;");
    };

    issue(0, 0);
    issue(1, 1);
    for (int kc = 0; kc < NKC16; ++kc) {
        if (kc < NKC16 - 1) asm volatile("cp.async.wait_group 1;");
        else                asm volatile("cp.async.wait_group 0;");
        __syncthreads();
        if (kc + 2 < NKC16) issue(kc + 2, (kc + 2) % GSTG);

        const __half* As = sA + (kc % GSTG) * GSTAGE;
        const __half* Bs = sB + (kc % GSTG) * GSTAGE;
        #pragma unroll
        for (int ks = 0; ks < 2; ++ks) {
            const int c = ks * 16 + lcol;
            uint32_t a[4][4], b[4][2];
            #pragma unroll
            for (int mt = 0; mt < 4; ++mt) {
                uint32_t ad = (uint32_t)__cvta_generic_to_shared(
                    As + (wm * 64 + mt * 16 + lrow) * GP16 + c);
                LDSM_X4(a[mt], ad);
            }
            #pragma unroll
            for (int nb = 0; nb < 2; ++nb) {
                uint32_t r[4];
                uint32_t ad = (uint32_t)__cvta_generic_to_shared(
                    Bs + (wn * 32 + nb * 16 + lrow) * GP16 + c);
                LDSM_X4(r, ad);
                // non-trans ldsm.x4: m0=(n0-7,k0-7) m1=(n8-15,k0-7) m2=(n0-7,k8-15) m3=(n8-15,k8-15)
                b[2 * nb][0] = r[0]; b[2 * nb][1] = r[2];
                b[2 * nb + 1][0] = r[1]; b[2 * nb + 1][1] = r[3];
            }
            #pragma unroll
            for (int mt = 0; mt < 4; ++mt)
                #pragma unroll
                for (int nt = 0; nt < 4; ++nt)
                    MMA_F16(acc[mt][nt], a[mt], b[nt]);
        }
    }
}

// ---------------------------------------------------------------------------
// Fused QKV GEMM: Bp = wqkvT [3072][1024] fp16. Outputs fp16 (Q scaled 0.125).
// ---------------------------------------------------------------------------
__global__ __launch_bounds__(256)
void gemm_qkv_h(const __half* __restrict__ Ap, const __half* __restrict__ Bp,
                const float* __restrict__ bq, const float* __restrict__ bk,
                const float* __restrict__ bv,
                __half* __restrict__ qo, __half* __restrict__ ko,
                __half* __restrict__ vo) {
    const int m0  = blockIdx.y * 128;
    const int n0g = blockIdx.x * 128;
    const int mat = blockIdx.x >> 3;
    const int n0  = (blockIdx.x & 7) * 128;
    const float* bias = (mat == 0) ? bq : (mat == 1) ? bk : bv;
    __half* C         = (mat == 0) ? qo : (mat == 1) ? ko : vo;
    const float osc   = (mat == 0) ? 0.125f : 1.0f;

    float acc[4][4][4];
    gemm16_core(Ap, Bp, m0, n0g, acc);

    const int lane = threadIdx.x & 31;
    const int wid  = threadIdx.x >> 5;
    const int wm   = wid >> 2, wn = wid & 3;
    const int g    = lane >> 2;
    #pragma unroll
    for (int mt = 0; mt < 4; ++mt) {
        const int r0 = m0 + wm * 64 + mt * 16 + g;
        #pragma unroll
        for (int nt = 0; nt < 4; ++nt) {
            const int col = n0 + wn * 32 + nt * 8 + (lane & 3) * 2;
            const float2 bv2 = *(const float2*)&bias[col];
            *(__half2*)&C[(size_t)r0 * NCOL + col] =
                __floats2half2_rn((acc[mt][nt][0] + bv2.x) * osc,
                                  (acc[mt][nt][1] + bv2.y) * osc);
            *(__half2*)&C[(size_t)(r0 + 8) * NCOL + col] =
                __floats2half2_rn((acc[mt][nt][2] + bv2.x) * osc,
                                  (acc[mt][nt][3] + bv2.y) * osc);
        }
    }
}

// ---------------------------------------------------------------------------
// Output projection GEMM: fp16 in, fp32 out.
// ---------------------------------------------------------------------------
__global__ __launch_bounds__(256)
void gemm_wo_h(const __half* __restrict__ Ap, const __half* __restrict__ Bp,
               const float* __restrict__ bias, float* __restrict__ C) {
    const int m0  = blockIdx.y * 128;
    const int n0g = blockIdx.x * 128;

    float acc[4][4][4];
    gemm16_core(Ap, Bp, m0, n0g, acc);

    const int lane = threadIdx.x & 31;
    const int wid  = threadIdx.x >> 5;
    const int wm   = wid >> 2, wn = wid & 3;
    const int g    = lane >> 2;
    #pragma unroll
    for (int mt = 0; mt < 4; ++mt) {
        const int r0 = m0 + wm * 64 + mt * 16 + g;
        #pragma unroll
        for (int nt = 0; nt < 4; ++nt) {
            const int col = n0g + wn * 32 + nt * 8 + (lane & 3) * 2;
            const float2 bv2 = *(const float2*)&bias[col];
            float2 o0, o1;
            o0.x = acc[mt][nt][0] + bv2.x;
            o0.y = acc[mt][nt][1] + bv2.y;
            o1.x = acc[mt][nt][2] + bv2.x;
            o1.y = acc[mt][nt][3] + bv2.y;
            *(float2*)&C[(size_t)r0 * NCOL + col] = o0;
            *(float2*)&C[(size_t)(r0 + 8) * NCOL + col] = o1;
        }
    }
}

// ---------------------------------------------------------------------------
// Causal flash attention, fp16 m16n8k16 MMA. 128 threads (4 warps x 16 rows).
// Inputs fp16 (Q pre-scaled by 0.125). P stays in registers (acc layout ==
// next A-frag layout). Output fp16.
// ---------------------------------------------------------------------------
#define FP 72   // smem pitch in halves (144B rows)

__global__ __launch_bounds__(128)
void flash_fp16(const __half* __restrict__ q, const __half* __restrict__ k,
                const __half* __restrict__ v, __half* __restrict__ o) {
    const int qt = (int)gridDim.x - 1 - blockIdx.x;  // long CTAs first
    const int h  = blockIdx.y;
    const int b  = blockIdx.z;

    __shared__ __half Qs[64 * FP];
    __shared__ __half Ks[64 * FP];
    __shared__ __half Vs[64 * FP];

    const int tid  = threadIdx.x;
    const int lane = tid & 31;
    const int w    = tid >> 5;
    const int g    = lane >> 2;
    const int t    = lane & 3;
    const int lrow = lane & 15;
    const int lcol = (lane >> 4) * 8;
    const int w16  = w * 16;
    const int q0   = qt * 64;

    // Load Q tile (fp16, already scaled)
    #pragma unroll
    for (int it = 0; it < 4; ++it) {
        int idx = tid + it * 128;
        int row = idx >> 3, ch = (idx & 7) * 8;
        CP_ASYNC16(&Qs[row * FP + ch],
                   q + (size_t)(b * T_SEQ + q0 + row) * NCOL + h * DH + ch);
    }
    asm volatile("cp.async.commit_group;");
    asm volatile("cp.async.wait_group 0;");
    __syncthreads();

    // Hoist Q A-fragments: 4 k16-steps
    uint32_t qa[4][4];
    #pragma unroll
    for (int j = 0; j < 4; ++j) {
        uint32_t ad = (uint32_t)__cvta_generic_to_shared(
            &Qs[(w16 + lrow) * FP + j * 16 + lcol]);
        LDSM_X4(qa[j], ad);
    }

    float mA = -1e30f, mB = -1e30f, lA = 0.f, lB = 0.f;
    float oacc[8][4];
    #pragma unroll
    for (int nt = 0; nt < 8; ++nt)
        #pragma unroll
        for (int r = 0; r < 4; ++r) oacc[nt][r] = 0.f;

    for (int kt = 0; kt <= qt; ++kt) {
        __syncthreads();   // all warps done reading Ks/Vs

        #pragma unroll
        for (int it = 0; it < 4; ++it) {
            int idx = tid + it * 128;
            int row = idx >> 3, ch = (idx & 7) * 8;
            size_t base = (size_t)(b * T_SEQ + kt * 64 + row) * NCOL + h * DH + ch;
            CP_ASYNC16(&Ks[row * FP + ch], k + base);
            CP_ASYNC16(&Vs[row * FP + ch], v + base);
        }
        asm volatile("cp.async.commit_group;");
        asm volatile("cp.async.wait_group 0;");
        __syncthreads();

        // S = Q K^T
        float sacc[8][4];
        #pragma unroll
        for (int nt = 0; nt < 8; ++nt)
            #pragma unroll
            for (int r = 0; r < 4; ++r) sacc[nt][r] = 0.f;

        #pragma unroll
        for (int j = 0; j < 4; ++j) {
            const int c = j * 16 + lcol;
            #pragma unroll
            for (int nb = 0; nb < 4; ++nb) {
                uint32_t r[4];
                uint32_t ad = (uint32_t)__cvta_generic_to_shared(
                    &Ks[(nb * 16 + lrow) * FP + c]);
                LDSM_X4(r, ad);
                uint32_t b0[2] = {r[0], r[2]};
                uint32_t b1[2] = {r[1], r[3]};
                MMA_F16(sacc[2 * nb], qa[j], b0);
                MMA_F16(sacc[2 * nb + 1], qa[j], b1);
            }
        }

        // Causal mask on diagonal tile
        if (kt == qt) {
            const int rA = w16 + g, rB = rA + 8;
            #pragma unroll
            for (int nt = 0; nt < 8; ++nt) {
                const int c0 = nt * 8 + 2 * t, c1 = c0 + 1;
                if (c0 > rA) sacc[nt][0] = -1e30f;
                if (c1 > rA) sacc[nt][1] = -1e30f;
                if (c0 > rB) sacc[nt][2] = -1e30f;
                if (c1 > rB) sacc[nt][3] = -1e30f;
            }
        }

        // Online softmax (register + quad shuffle)
        float rmA = -1e30f, rmB = -1e30f;
        #pragma unroll
        for (int nt = 0; nt < 8; ++nt) {
            rmA = fmaxf(rmA, fmaxf(sacc[nt][0], sacc[nt][1]));
            rmB = fmaxf(rmB, fmaxf(sacc[nt][2], sacc[nt][3]));
        }
        rmA = fmaxf(rmA, __shfl_xor_sync(0xffffffffu, rmA, 1));
        rmA = fmaxf(rmA, __shfl_xor_sync(0xffffffffu, rmA, 2));
        rmB = fmaxf(rmB, __shfl_xor_sync(0xffffffffu, rmB, 1));
        rmB = fmaxf(rmB, __shfl_xor_sync(0xffffffffu, rmB, 2));

        const float mnA = fmaxf(mA, rmA);
        const float mnB = fmaxf(mB, rmB);
        const float cA = __expf(mA - mnA);
        const float cB = __expf(mB - mnB);

        float sA = 0.f, sB = 0.f;
        #pragma unroll
        for (int nt = 0; nt < 8; ++nt) {
            sacc[nt][0] = __expf(sacc[nt][0] - mnA);
            sacc[nt][1] = __expf(sacc[nt][1] - mnA);
            sacc[nt][2] = __expf(sacc[nt][2] - mnB);
            sacc[nt][3] = __expf(sacc[nt][3] - mnB);
            sA += sacc[nt][0] + sacc[nt][1];
            sB += sacc[nt][2] + sacc[nt][3];
        }
        sA += __shfl_xor_sync(0xffffffffu, sA, 1);
        sA += __shfl_xor_sync(0xffffffffu, sA, 2);
        sB += __shfl_xor_sync(0xffffffffu, sB, 1);
        sB += __shfl_xor_sync(0xffffffffu, sB, 2);
        lA = lA * cA + sA;
        lB = lB * cB + sB;
        mA = mnA;
        mB = mnB;

        #pragma unroll
        for (int nt = 0; nt < 8; ++nt) {
            oacc[nt][0] *= cA; oacc[nt][1] *= cA;
            oacc[nt][2] *= cB; oacc[nt][3] *= cB;
        }

        // Pack P into fp16 A-fragments (register-only; C layout == A layout)
        uint32_t pa[4][4];
        #pragma unroll
        for (int j = 0; j < 4; ++j) {
            pa[j][0] = pack_h2(sacc[2 * j][0],     sacc[2 * j][1]);
            pa[j][1] = pack_h2(sacc[2 * j][2],     sacc[2 * j][3]);
            pa[j][2] = pack_h2(sacc[2 * j + 1][0], sacc[2 * j + 1][1]);
            pa[j][3] = pack_h2(sacc[2 * j + 1][2], sacc[2 * j + 1][3]);
        }

        // O += P @ V  (V frags via ldmatrix.trans)
        #pragma unroll
        for (int j = 0; j < 4; ++j) {
            #pragma unroll
            for (int nb = 0; nb < 4; ++nb) {
                uint32_t r[4];
                uint32_t ad = (uint32_t)__cvta_generic_to_shared(
                    &Vs[(j * 16 + lrow) * FP + nb * 16 + lcol]);
                LDSM_X4_T(r, ad);
                uint32_t b0[2] = {r[0], r[1]};
                uint32_t b1[2] = {r[2], r[3]};
                MMA_F16(oacc[2 * nb], pa[j], b0);
                MMA_F16(oacc[2 * nb + 1], pa[j], b1);
            }
        }
    }

    // Epilogue: normalize, fp16 out
    const float invA = 1.0f / lA;
    const float invB = 1.0f / lB;
    const int rA = b * T_SEQ + q0 + w16 + g;
    const int rB = rA + 8;
    #pragma unroll
    for (int nt = 0; nt < 8; ++nt) {
        const int col = h * DH + nt * 8 + 2 * t;
        *(__half2*)&o[(size_t)rA * NCOL + col] =
            __floats2half2_rn(oacc[nt][0] * invA, oacc[nt][1] * invA);
        *(__half2*)&o[(size_t)rB * NCOL + col] =
            __floats2half2_rn(oacc[nt][2] * invB, oacc[nt][3] * invB);
    }
}

// ---------------------------------------------------------------------------
// Launch
// ---------------------------------------------------------------------------
extern "C" void kernel_launch(void* const* d_in, const int* in_sizes, int n_in,
                              void* d_out, int out_size) {
    const float* x  = (const float*)d_in[0];
    const float* wq = (const float*)d_in[1];
    const float* bq = (const float*)d_in[2];
    const float* wk = (const float*)d_in[3];
    const float* bk = (const float*)d_in[4];
    const float* wv = (const float*)d_in[5];
    const float* bv = (const float*)d_in[6];
    const float* wo = (const float*)d_in[7];
    const float* bo = (const float*)d_in[8];
    float* out = (float*)d_out;

    unsigned char* sp;
    cudaGetSymbolAddress((void**)&sp, g_scratch);
    const size_t MB = 1024u * 1024u;
    __half* qp    = (__half*)(sp + 0 * MB);
    __half* kp    = (__half*)(sp + 8 * MB);
    __half* vp    = (__half*)(sp + 16 * MB);
    __half* ap    = (__half*)(sp + 24 * MB);
    __half* xh    = (__half*)(sp + 32 * MB);
    __half* wqkvT = (__half*)(sp + 40 * MB);   // 3 x 2MB contiguous
    __half* woT   = (__half*)(sp + 46 * MB);

    cudaFuncSetAttribute(gemm_qkv_h,
                         cudaFuncAttributeMaxDynamicSharedMemorySize, GEMM_SMEM);
    cudaFuncSetAttribute(gemm_wo_h,
                         cudaFuncAttributeMaxDynamicSharedMemorySize, GEMM_SMEM);

    // 1) x -> fp16
    const int n4 = M_TOT * D_MOD / 4;
    cvt_half4<<<(n4 + 255) / 256, 256>>>(x, xh, n4);

    // 2) Transpose + fp16 weights -> wT[N][K]
    dim3 tg(NCOL / 32, D_MOD / 32), tb(32, 8);
    cvt_T_half<<<tg, tb>>>(wq, wqkvT);
    cvt_T_half<<<tg, tb>>>(wk, wqkvT + 1024 * 1024);
    cvt_T_half<<<tg, tb>>>(wv, wqkvT + 2 * 1024 * 1024);
    cvt_T_half<<<tg, tb>>>(wo, woT);

    // 3) Fused QKV projection (fp16 out; Q pre-scaled by 0.125)
    gemm_qkv_h<<<dim3(24, M_TOT / 128), 256, GEMM_SMEM>>>(
        xh, wqkvT, bq, bk, bv, qp, kp, vp);

    // 4) Attention (fp16 MMA)
    flash_fp16<<<dim3(T_SEQ / 64, NH, B_SZ), 128>>>(qp, kp, vp, ap);

    // 5) Output projection (fp32 out)
    gemm_wo_h<<<dim3(NCOL / 128, M_TOT / 128), 256, GEMM_SMEM>>>(ap, woT, bo, out);
}